// round 2
// baseline (speedup 1.0000x reference)
#include <cuda_runtime.h>
#include <math.h>

// Problem constants
#define BB 32        // batch
#define TT 512       // time steps
#define II 1024      // input dim
#define HH 1024      // hidden dim
#define G4 4096      // 4*H
#define MROWS (TT*BB)          // 16384
#define BH (BB*HH)             // 32768
#define NCTA 128
#define NTHR 512

// ---------------- scratch (static device arrays; no cudaMalloc allowed) ----------------
__device__ __align__(128) float g_gx[(size_t)MROWS * G4];     // 256 MB hoisted input projection
__device__ __align__(128) float g_h0seq[(size_t)MROWS * HH];  // 64 MB layer-0 outputs [t][b][j]
__device__ __align__(128) float g_hbuf[2][HH * BB];           // h double buffer, TRANSPOSED [k][b]
__device__ float g_c0[BH];
__device__ float g_c1[BH];
__device__ unsigned int g_barcnt;

// smem layout (floats)
#define WS_OFF   0                         // Ws[k][32]        : 32768
#define HS_OFF   (WS_OFF + 1024*32)        // hs[128][32]      : 4096
#define PART_OFF (HS_OFF + 128*32)         // part[8*32][33]   : 8448
#define CS_OFF   (PART_OFF + 8*32*33)      // cs[256]          : 256
#define SMEM_FLOATS (CS_OFF + 256)
#define SMEM_BYTES (SMEM_FLOATS * 4)       // 182272 B

// ---------------- big GEMM: C[M,N] = A[M,K] @ W[N,K]^T + b1[n] + b2[n] ----------------
// MODE 0: A row m contiguous at A + m*K
// MODE 1: A row m gathers from x[B,T,I]: offset ((m%32)*512 + m/32) * K   (m = t*32 + b)
template <int MODE>
__global__ __launch_bounds__(256) void gemm_bias(
    const float* __restrict__ A, const float* __restrict__ W,
    const float* __restrict__ b1, const float* __restrict__ b2,
    float* __restrict__ C, int M, int N, int K)
{
    __shared__ float As[8][128];
    __shared__ float Bs[8][128];

    const int tid = threadIdx.x;
    const int n0 = blockIdx.x * 128;
    const int m0 = blockIdx.y * 128;

    const int lr  = tid >> 1;
    const int lk4 = (tid & 1) * 4;
    const int rm = (tid & 15) * 8;
    const int rn = (tid >> 4) * 8;

    float acc[8][8];
#pragma unroll
    for (int i = 0; i < 8; i++)
#pragma unroll
        for (int j = 0; j < 8; j++) acc[i][j] = 0.f;

    for (int k0 = 0; k0 < K; k0 += 8) {
        {
            int row = m0 + lr;
            size_t off;
            if (MODE == 0) off = (size_t)row * K;
            else           off = (size_t)((row & 31) * 512 + (row >> 5)) * K;
            float4 a = *(const float4*)&A[off + k0 + lk4];
            As[lk4 + 0][lr] = a.x; As[lk4 + 1][lr] = a.y;
            As[lk4 + 2][lr] = a.z; As[lk4 + 3][lr] = a.w;
        }
        {
            int n = n0 + lr;
            float4 b = *(const float4*)&W[(size_t)n * K + k0 + lk4];
            Bs[lk4 + 0][lr] = b.x; Bs[lk4 + 1][lr] = b.y;
            Bs[lk4 + 2][lr] = b.z; Bs[lk4 + 3][lr] = b.w;
        }
        __syncthreads();

#pragma unroll
        for (int k = 0; k < 8; k++) {
            float a0[8], b0[8];
            float4 av0 = *(const float4*)&As[k][rm];
            float4 av1 = *(const float4*)&As[k][rm + 4];
            float4 bv0 = *(const float4*)&Bs[k][rn];
            float4 bv1 = *(const float4*)&Bs[k][rn + 4];
            a0[0]=av0.x; a0[1]=av0.y; a0[2]=av0.z; a0[3]=av0.w;
            a0[4]=av1.x; a0[5]=av1.y; a0[6]=av1.z; a0[7]=av1.w;
            b0[0]=bv0.x; b0[1]=bv0.y; b0[2]=bv0.z; b0[3]=bv0.w;
            b0[4]=bv1.x; b0[5]=bv1.y; b0[6]=bv1.z; b0[7]=bv1.w;
#pragma unroll
            for (int i = 0; i < 8; i++)
#pragma unroll
                for (int j = 0; j < 8; j++)
                    acc[i][j] = fmaf(a0[i], b0[j], acc[i][j]);
        }
        __syncthreads();
    }

#pragma unroll
    for (int i = 0; i < 8; i++) {
        int row = m0 + rm + i;
#pragma unroll
        for (int j4 = 0; j4 < 8; j4 += 4) {
            int n = n0 + rn + j4;
            float4 v;
            v.x = acc[i][j4 + 0] + b1[n + 0] + b2[n + 0];
            v.y = acc[i][j4 + 1] + b1[n + 1] + b2[n + 1];
            v.z = acc[i][j4 + 2] + b1[n + 2] + b2[n + 2];
            v.w = acc[i][j4 + 3] + b1[n + 3] + b2[n + 3];
            *(float4*)&C[(size_t)row * N + n] = v;
        }
    }
}

// ---------------- persistent LSTM layer: one launch, 512 steps, grid barrier ----------------
__global__ void __launch_bounds__(NTHR, 1) lstm_layer_persistent(
    const float* __restrict__ Whh,   // [4096][1024]
    const float* __restrict__ gx,    // [T*B][4096]  (t*32+b major)
    float* __restrict__ seq,         // [T][B][H]
    float* __restrict__ c_out)       // [B][H]
{
    extern __shared__ float sm[];
    float* Ws   = sm + WS_OFF;    // Ws[k*32 + r], r = g*8 + jl
    float* hs   = sm + HS_OFF;    // hs[kl*32 + b]
    float* part = sm + PART_OFF;  // part[(s*32 + r)*33 + b]
    float* cs   = sm + CS_OFF;    // cs[b*8 + jl] == cs[tid] for tid<256

    const int tid = threadIdx.x;
    const int cta = blockIdx.x;           // j block = cta*8
    const int s  = tid >> 6;              // 0..7 k-subslice
    const int u  = tid & 63;
    const int ty = u >> 3;                // 0..7 (4 rows each)
    const int tx = u & 7;                 // 0..7 (4 batches each)

    // one-time: W slice -> smem (coalesced LDG; conflicted STS is fine once)
    for (int idx = tid; idx < 32 * 1024; idx += NTHR) {
        int r = idx >> 10;                // 0..31
        int k = idx & 1023;
        int g = r >> 3, jl = r & 7;
        Ws[k * 32 + r] = Whh[(size_t)(g * 1024 + cta * 8 + jl) * HH + k];
    }
    if (tid < 256) cs[tid] = 0.f;
    __syncthreads();

    const int jl_b = tid & 7;
    const int b_b  = tid >> 3;            // valid when tid < 256

    float acc[4][4];

    for (int t = 0; t < TT; t++) {
        const float* hcur = g_hbuf[t & 1];
        float*       hnxt = g_hbuf[(t + 1) & 1];

        // prefetch gx for phase B (HBM latency hidden behind phase A)
        float gxr0 = 0.f, gxr1 = 0.f, gxr2 = 0.f, gxr3 = 0.f;
        if (tid < 256) {
            const float* gp = gx + (size_t)(t * 32 + b_b) * G4 + cta * 8 + jl_b;
            gxr0 = __ldg(gp);
            gxr1 = __ldg(gp + 1024);
            gxr2 = __ldg(gp + 2048);
            gxr3 = __ldg(gp + 3072);
        }

#pragma unroll
        for (int i = 0; i < 4; i++)
#pragma unroll
            for (int j = 0; j < 4; j++) acc[i][j] = 0.f;

        // prefetch h chunk 0 (L2-coherent)
        float4 pre0 = __ldcg((const float4*)hcur + tid * 2);
        float4 pre1 = __ldcg((const float4*)hcur + tid * 2 + 1);

        for (int cn = 0; cn < 8; cn++) {
            __syncthreads();                              // hs writable
            ((float4*)hs)[tid * 2]     = pre0;
            ((float4*)hs)[tid * 2 + 1] = pre1;
            __syncthreads();                              // hs[cn] ready
            if (cn < 7) {
                const float4* src = (const float4*)(hcur + (cn + 1) * 4096);
                pre0 = __ldcg(src + tid * 2);
                pre1 = __ldcg(src + tid * 2 + 1);
            }
            const float* WsK = Ws + (cn * 128 + s * 16) * 32;
            const float* hsK = hs + (s * 16) * 32;
#pragma unroll
            for (int kl = 0; kl < 16; kl++) {
                float4 wv = *(const float4*)(WsK + kl * 32 + ty * 4);
                float4 hv = *(const float4*)(hsK + kl * 32 + tx * 4);
                acc[0][0] = fmaf(wv.x, hv.x, acc[0][0]);
                acc[0][1] = fmaf(wv.x, hv.y, acc[0][1]);
                acc[0][2] = fmaf(wv.x, hv.z, acc[0][2]);
                acc[0][3] = fmaf(wv.x, hv.w, acc[0][3]);
                acc[1][0] = fmaf(wv.y, hv.x, acc[1][0]);
                acc[1][1] = fmaf(wv.y, hv.y, acc[1][1]);
                acc[1][2] = fmaf(wv.y, hv.z, acc[1][2]);
                acc[1][3] = fmaf(wv.y, hv.w, acc[1][3]);
                acc[2][0] = fmaf(wv.z, hv.x, acc[2][0]);
                acc[2][1] = fmaf(wv.z, hv.y, acc[2][1]);
                acc[2][2] = fmaf(wv.z, hv.z, acc[2][2]);
                acc[2][3] = fmaf(wv.z, hv.w, acc[2][3]);
                acc[3][0] = fmaf(wv.w, hv.x, acc[3][0]);
                acc[3][1] = fmaf(wv.w, hv.y, acc[3][1]);
                acc[3][2] = fmaf(wv.w, hv.z, acc[3][2]);
                acc[3][3] = fmaf(wv.w, hv.w, acc[3][3]);
            }
        }

        // k-slice partials
#pragma unroll
        for (int i = 0; i < 4; i++)
#pragma unroll
            for (int j = 0; j < 4; j++)
                part[(s * 32 + ty * 4 + i) * 33 + tx * 4 + j] = acc[i][j];
        __syncthreads();

        // phase B: reduce + gates + state update (threads 0..255: (b, jl))
        if (tid < 256) {
            float gsum[4];
#pragma unroll
            for (int g = 0; g < 4; g++) {
                float v = 0.f;
#pragma unroll
                for (int ss = 0; ss < 8; ss++)
                    v += part[(ss * 32 + g * 8 + jl_b) * 33 + b_b];
                gsum[g] = v;
            }
            gsum[0] += gxr0; gsum[1] += gxr1; gsum[2] += gxr2; gsum[3] += gxr3;

            float ig = 1.f / (1.f + expf(-gsum[0]));
            float fg = 1.f / (1.f + expf(-gsum[1]));
            float gg = tanhf(gsum[2]);
            float og = 1.f / (1.f + expf(-gsum[3]));
            float cprev = cs[tid];
            float cnew = fg * cprev + ig * gg;
            float hnew = og * tanhf(cnew);
            cs[tid] = cnew;
            __stcg(&hnxt[(cta * 8 + jl_b) * 32 + b_b], hnew);   // transposed [k][b]
            seq[(size_t)t * BH + (size_t)b_b * 1024 + cta * 8 + jl_b] = hnew;
        }

        // grid barrier (skip after last step)
        __threadfence();
        if (t < TT - 1) {
            __syncthreads();
            if (tid == 0) {
                atomicAdd(&g_barcnt, 1u);
                unsigned target = (unsigned)(t + 1) * NCTA;
                volatile unsigned* p = &g_barcnt;
                while (*p < target) { }
            }
            __syncthreads();
        }
    }

    if (tid < 256)
        c_out[(size_t)b_b * 1024 + cta * 8 + jl_b] = cs[tid];
}

// ---------------- helpers ----------------
__global__ void reset_kernel()
{
    int idx = blockIdx.x * blockDim.x + threadIdx.x;
    if (idx == 0) g_barcnt = 0u;
    if (idx < HH * BB) g_hbuf[0][idx] = 0.f;
}

__global__ void finalize(const float* __restrict__ h0seq,
                         const float* __restrict__ out,
                         const float* __restrict__ c0,
                         const float* __restrict__ c1,
                         float* __restrict__ dst)
{
    int idx = blockIdx.x * blockDim.x + threadIdx.x;
    if (idx < BH) {
        dst[idx]          = h0seq[(size_t)(TT - 1) * BH + idx];  // h final L0
        dst[BH + idx]     = out[(size_t)(TT - 1) * BH + idx];    // h final L1
        dst[2 * BH + idx] = c0[idx];                             // c final L0
        dst[3 * BH + idx] = c1[idx];                             // c final L1
    }
}

// ---------------- launch ----------------
extern "C" void kernel_launch(void* const* d_in, const int* in_sizes, int n_in,
                              void* d_out, int out_size)
{
    const float* x     = (const float*)d_in[0];
    const float* W_ih0 = (const float*)d_in[1];
    const float* W_hh0 = (const float*)d_in[2];
    const float* b_ih0 = (const float*)d_in[3];
    const float* b_hh0 = (const float*)d_in[4];
    const float* W_ih1 = (const float*)d_in[5];
    const float* W_hh1 = (const float*)d_in[6];
    const float* b_ih1 = (const float*)d_in[7];
    const float* b_hh1 = (const float*)d_in[8];
    float* out = (float*)d_out;

    float *gx, *h0seq, *c0, *c1;
    cudaGetSymbolAddress((void**)&gx,    g_gx);
    cudaGetSymbolAddress((void**)&h0seq, g_h0seq);
    cudaGetSymbolAddress((void**)&c0,    g_c0);
    cudaGetSymbolAddress((void**)&c1,    g_c1);

    cudaFuncSetAttribute(lstm_layer_persistent,
                         cudaFuncAttributeMaxDynamicSharedMemorySize, SMEM_BYTES);

    dim3 gemm_grid(G4 / 128, MROWS / 128);   // (32, 128)

    // ---- layer 0 ----
    gemm_bias<1><<<gemm_grid, 256>>>(x, W_ih0, b_ih0, b_hh0, gx, MROWS, G4, II);
    reset_kernel<<<128, 256>>>();
    lstm_layer_persistent<<<NCTA, NTHR, SMEM_BYTES>>>(W_hh0, gx, h0seq, c0);

    // ---- layer 1 ----
    gemm_bias<0><<<gemm_grid, 256>>>(h0seq, W_ih1, b_ih1, b_hh1, gx, MROWS, G4, HH);
    reset_kernel<<<128, 256>>>();
    lstm_layer_persistent<<<NCTA, NTHR, SMEM_BYTES>>>(W_hh1, gx, out, c1);

    // ---- tails: [h0_T, h1_T, c0_T, c1_T] ----
    finalize<<<(BH + 255) / 256, 256>>>(h0seq, out, c0, c1, out + (size_t)TT * BH);
}

// round 5
// speedup vs baseline: 1.2830x; 1.2830x over previous
#include <cuda_runtime.h>
#include <cuda_bf16.h>
#include <math.h>
#include <stdint.h>

// Problem constants
#define BB 32
#define TT 512
#define II 1024
#define HH 1024
#define G4 4096
#define MROWS (TT*BB)          // 16384
#define BH (BB*HH)             // 32768
#define NCTA 128
#define NTHR 512

// ---------------- static scratch ----------------
__device__ __align__(128) float g_gx[(size_t)MROWS * G4];       // 256 MB
__device__ __align__(128) float g_h0seq[(size_t)MROWS * HH];    // 64 MB
__device__ __align__(16) __nv_bfloat16 g_ahi[(size_t)MROWS * HH];  // 32 MB
__device__ __align__(16) __nv_bfloat16 g_alo[(size_t)MROWS * HH];  // 32 MB
__device__ __align__(16) __nv_bfloat16 g_whi[(size_t)G4 * HH];     // 8 MB
__device__ __align__(16) __nv_bfloat16 g_wlo[(size_t)G4 * HH];     // 8 MB
__device__ __align__(128) float g_hbuf[2][HH * BB];
__device__ float g_c0[BH];
__device__ float g_c1[BH];
__device__ unsigned int g_barcnt;

// ==================== PTX helpers (plain sm_103-legal only) ====================
__device__ __forceinline__ uint32_t smem_u32(const void* p) {
    uint32_t a;
    asm("{ .reg .u64 t; cvta.to.shared.u64 t, %1; cvt.u32.u64 %0, t; }" : "=r"(a) : "l"(p));
    return a;
}
__device__ __forceinline__ void cp16(uint32_t d, const void* s) {
    asm volatile("cp.async.cg.shared.global [%0], [%1], 16;" :: "r"(d), "l"(s));
}
__device__ __forceinline__ void cp_commit() {
    asm volatile("cp.async.commit_group;" ::: "memory");
}
template <int N>
__device__ __forceinline__ void cp_wait() {
    asm volatile("cp.async.wait_group %0;" :: "n"(N) : "memory");
}
__device__ __forceinline__ void ldsm_x4(uint32_t* r, uint32_t addr) {
    asm volatile("ldmatrix.sync.aligned.m8n8.x4.shared.b16 {%0,%1,%2,%3}, [%4];"
        : "=r"(r[0]), "=r"(r[1]), "=r"(r[2]), "=r"(r[3]) : "r"(addr));
}
__device__ __forceinline__ void ldsm_x2(uint32_t* r, uint32_t addr) {
    asm volatile("ldmatrix.sync.aligned.m8n8.x2.shared.b16 {%0,%1}, [%2];"
        : "=r"(r[0]), "=r"(r[1]) : "r"(addr));
}
__device__ __forceinline__ void mma16816(float* d, const uint32_t* a, const uint32_t* b) {
    asm volatile(
        "mma.sync.aligned.m16n8k16.row.col.f32.bf16.bf16.f32 "
        "{%0,%1,%2,%3}, {%4,%5,%6,%7}, {%8,%9}, {%0,%1,%2,%3};"
        : "+f"(d[0]), "+f"(d[1]), "+f"(d[2]), "+f"(d[3])
        : "r"(a[0]), "r"(a[1]), "r"(a[2]), "r"(a[3]), "r"(b[0]), "r"(b[1]));
}

// ==================== split-bf16 conversion ====================
// gather=1: row m of A maps to x[(m%32)][m/32] (x is [B,T,I]); rows are t*32+b
__global__ __launch_bounds__(256) void conv_split(
    const float* __restrict__ src, __nv_bfloat16* __restrict__ hi,
    __nv_bfloat16* __restrict__ lo, int gather)
{
    size_t idx = (size_t)blockIdx.x * 256 + threadIdx.x;
    size_t soff;
    if (gather) {
        int m = (int)(idx >> 10);
        int k = (int)(idx & 1023);
        soff = (size_t)((m & 31) * 512 + (m >> 5)) * 1024 + k;
    } else {
        soff = idx;
    }
    float v = src[soff];
    __nv_bfloat16 h = __float2bfloat16(v);
    hi[idx] = h;
    lo[idx] = __float2bfloat16(v - __bfloat162float(h));
}

// ==================== HMMA GEMM ====================
// C[16384, 4096] = A[·,1024] @ W[·,1024]^T + b1[n] + b2[n]
// split-bf16: Ahi*Whi + Ahi*Wlo + Alo*Whi, fp32 accumulators.
// BM=128 BN=128 BK=32, 8 warps (2m x 4n), 80B-padded smem rows (conflict-free ldmatrix).
#define ROWB 80
#define TILE_B (128 * ROWB)             // 10240 B per tile
#define STAGE_B (4 * TILE_B)            // 40960 B per stage
#define MG_SMEM (2 * STAGE_B)           // 81920 B

__global__ __launch_bounds__(256) void mma_gemm(
    const __nv_bfloat16* __restrict__ Ahi, const __nv_bfloat16* __restrict__ Alo,
    const __nv_bfloat16* __restrict__ Whi, const __nv_bfloat16* __restrict__ Wlo,
    const float* __restrict__ b1, const float* __restrict__ b2,
    float* __restrict__ C)
{
    extern __shared__ char smraw[];
    const uint32_t sbase = smem_u32(smraw);

    const int tid = threadIdx.x;
    const int wid = tid >> 5;
    const int lid = tid & 31;
    const int wm = wid & 1;              // 2 m-warps (64 rows each)
    const int wn = wid >> 1;             // 4 n-warps (32 cols each)
    const int n0 = blockIdx.x * 128;
    const int m0 = blockIdx.y * 128;

    // per-lane ldmatrix offsets (relative to tile base, bytes)
    uint32_t aoff[4], boff[4];
#pragma unroll
    for (int i = 0; i < 4; i++) {
        int row = wm * 64 + i * 16 + (lid & 15);
        aoff[i] = (uint32_t)(row * ROWB + (lid >> 4) * 16);
    }
#pragma unroll
    for (int j = 0; j < 4; j++) {
        int row = wn * 32 + j * 8 + (lid & 7);
        boff[j] = (uint32_t)(row * ROWB + ((lid >> 3) & 1) * 16);
    }

    float acc[4][4][4];
#pragma unroll
    for (int i = 0; i < 4; i++)
#pragma unroll
        for (int j = 0; j < 4; j++)
#pragma unroll
            for (int q = 0; q < 4; q++) acc[i][j][q] = 0.f;

    // cp.async loader: 2048 x 16B per stage, 8 per thread
    auto issue_stage = [&](int kc, int st) {
        const int k0 = kc * 32;
        const uint32_t sb = sbase + st * STAGE_B;
#pragma unroll
        for (int it = 0; it < 8; it++) {
            int idx = it * 256 + tid;
            int tl = idx >> 9;           // tile 0..3
            int w  = idx & 511;
            int r  = w >> 2;             // row 0..127
            int q  = w & 3;              // 16B chunk within 64B row
            const __nv_bfloat16* src;
            if (tl == 0)      src = Ahi + (size_t)(m0 + r) * 1024 + k0 + q * 8;
            else if (tl == 1) src = Alo + (size_t)(m0 + r) * 1024 + k0 + q * 8;
            else if (tl == 2) src = Whi + (size_t)(n0 + r) * 1024 + k0 + q * 8;
            else              src = Wlo + (size_t)(n0 + r) * 1024 + k0 + q * 8;
            cp16(sb + tl * TILE_B + r * ROWB + q * 16, src);
        }
        cp_commit();
    };

    issue_stage(0, 0);

#pragma unroll 1
    for (int kc = 0; kc < 32; kc++) {
        const int st = kc & 1;
        if (kc + 1 < 32) { issue_stage(kc + 1, st ^ 1); cp_wait<1>(); }
        else             { cp_wait<0>(); }
        __syncthreads();

        const uint32_t sA_hi = sbase + st * STAGE_B;
        const uint32_t sA_lo = sA_hi + TILE_B;
        const uint32_t sW_hi = sA_hi + 2 * TILE_B;
        const uint32_t sW_lo = sA_hi + 3 * TILE_B;

#pragma unroll
        for (int ks = 0; ks < 2; ks++) {
            const uint32_t kb = ks * 32;    // 16 bf16 = 32 bytes
            uint32_t ah[4][4], al[4][4], bh[4][2], bl[4][2];
#pragma unroll
            for (int i = 0; i < 4; i++) ldsm_x4(ah[i], sA_hi + aoff[i] + kb);
#pragma unroll
            for (int i = 0; i < 4; i++) ldsm_x4(al[i], sA_lo + aoff[i] + kb);
#pragma unroll
            for (int j = 0; j < 4; j++) ldsm_x2(bh[j], sW_hi + boff[j] + kb);
#pragma unroll
            for (int j = 0; j < 4; j++) ldsm_x2(bl[j], sW_lo + boff[j] + kb);

#pragma unroll
            for (int i = 0; i < 4; i++)
#pragma unroll
                for (int j = 0; j < 4; j++) {
                    mma16816(acc[i][j], ah[i], bh[j]);
                    mma16816(acc[i][j], ah[i], bl[j]);
                    mma16816(acc[i][j], al[i], bh[j]);
                }
        }
        __syncthreads();
    }

    // epilogue: bias add + direct store
    const int gi = lid >> 2;
    const int ti = lid & 3;
#pragma unroll
    for (int i = 0; i < 4; i++) {
        int mlo = m0 + wm * 64 + i * 16 + gi;
#pragma unroll
        for (int j = 0; j < 4; j++) {
            int n = n0 + wn * 32 + j * 8 + ti * 2;
            float bs0 = __ldg(&b1[n]) + __ldg(&b2[n]);
            float bs1 = __ldg(&b1[n + 1]) + __ldg(&b2[n + 1]);
            float2 v0 = make_float2(acc[i][j][0] + bs0, acc[i][j][1] + bs1);
            float2 v1 = make_float2(acc[i][j][2] + bs0, acc[i][j][3] + bs1);
            *(float2*)&C[(size_t)mlo * G4 + n] = v0;
            *(float2*)&C[(size_t)(mlo + 8) * G4 + n] = v1;
        }
    }
}

// ==================== persistent LSTM layer (validated in R2) ====================
#define WS_OFF   0
#define HS_OFF   (WS_OFF + 1024*32)
#define PART_OFF (HS_OFF + 128*32)
#define CS_OFF   (PART_OFF + 8*32*33)
#define SMEM_FLOATS (CS_OFF + 256)
#define SMEM_BYTES (SMEM_FLOATS * 4)

__global__ void __launch_bounds__(NTHR, 1) lstm_layer_persistent(
    const float* __restrict__ Whh,
    const float* __restrict__ gx,
    float* __restrict__ seq,
    float* __restrict__ c_out)
{
    extern __shared__ float sm[];
    float* Ws   = sm + WS_OFF;
    float* hs   = sm + HS_OFF;
    float* part = sm + PART_OFF;
    float* cs   = sm + CS_OFF;

    const int tid = threadIdx.x;
    const int cta = blockIdx.x;
    const int s  = tid >> 6;
    const int u  = tid & 63;
    const int ty = u >> 3;
    const int tx = u & 7;

    for (int idx = tid; idx < 32 * 1024; idx += NTHR) {
        int r = idx >> 10;
        int k = idx & 1023;
        int g = r >> 3, jl = r & 7;
        Ws[k * 32 + r] = Whh[(size_t)(g * 1024 + cta * 8 + jl) * HH + k];
    }
    if (tid < 256) cs[tid] = 0.f;
    __syncthreads();

    const int jl_b = tid & 7;
    const int b_b  = tid >> 3;

    float acc[4][4];

    for (int t = 0; t < TT; t++) {
        const float* hcur = g_hbuf[t & 1];
        float*       hnxt = g_hbuf[(t + 1) & 1];

        float gxr0 = 0.f, gxr1 = 0.f, gxr2 = 0.f, gxr3 = 0.f;
        if (tid < 256) {
            const float* gp = gx + (size_t)(t * 32 + b_b) * G4 + cta * 8 + jl_b;
            gxr0 = __ldg(gp);
            gxr1 = __ldg(gp + 1024);
            gxr2 = __ldg(gp + 2048);
            gxr3 = __ldg(gp + 3072);
        }

#pragma unroll
        for (int i = 0; i < 4; i++)
#pragma unroll
            for (int j = 0; j < 4; j++) acc[i][j] = 0.f;

        float4 pre0 = __ldcg((const float4*)hcur + tid * 2);
        float4 pre1 = __ldcg((const float4*)hcur + tid * 2 + 1);

        for (int cn = 0; cn < 8; cn++) {
            __syncthreads();
            ((float4*)hs)[tid * 2]     = pre0;
            ((float4*)hs)[tid * 2 + 1] = pre1;
            __syncthreads();
            if (cn < 7) {
                const float4* src = (const float4*)(hcur + (cn + 1) * 4096);
                pre0 = __ldcg(src + tid * 2);
                pre1 = __ldcg(src + tid * 2 + 1);
            }
            const float* WsK = Ws + (cn * 128 + s * 16) * 32;
            const float* hsK = hs + (s * 16) * 32;
#pragma unroll
            for (int kl = 0; kl < 16; kl++) {
                float4 wv = *(const float4*)(WsK + kl * 32 + ty * 4);
                float4 hv = *(const float4*)(hsK + kl * 32 + tx * 4);
                acc[0][0] = fmaf(wv.x, hv.x, acc[0][0]);
                acc[0][1] = fmaf(wv.x, hv.y, acc[0][1]);
                acc[0][2] = fmaf(wv.x, hv.z, acc[0][2]);
                acc[0][3] = fmaf(wv.x, hv.w, acc[0][3]);
                acc[1][0] = fmaf(wv.y, hv.x, acc[1][0]);
                acc[1][1] = fmaf(wv.y, hv.y, acc[1][1]);
                acc[1][2] = fmaf(wv.y, hv.z, acc[1][2]);
                acc[1][3] = fmaf(wv.y, hv.w, acc[1][3]);
                acc[2][0] = fmaf(wv.z, hv.x, acc[2][0]);
                acc[2][1] = fmaf(wv.z, hv.y, acc[2][1]);
                acc[2][2] = fmaf(wv.z, hv.z, acc[2][2]);
                acc[2][3] = fmaf(wv.z, hv.w, acc[2][3]);
                acc[3][0] = fmaf(wv.w, hv.x, acc[3][0]);
                acc[3][1] = fmaf(wv.w, hv.y, acc[3][1]);
                acc[3][2] = fmaf(wv.w, hv.z, acc[3][2]);
                acc[3][3] = fmaf(wv.w, hv.w, acc[3][3]);
            }
        }

#pragma unroll
        for (int i = 0; i < 4; i++)
#pragma unroll
            for (int j = 0; j < 4; j++)
                part[(s * 32 + ty * 4 + i) * 33 + tx * 4 + j] = acc[i][j];
        __syncthreads();

        if (tid < 256) {
            float gsum[4];
#pragma unroll
            for (int g = 0; g < 4; g++) {
                float v = 0.f;
#pragma unroll
                for (int ss = 0; ss < 8; ss++)
                    v += part[(ss * 32 + g * 8 + jl_b) * 33 + b_b];
                gsum[g] = v;
            }
            gsum[0] += gxr0; gsum[1] += gxr1; gsum[2] += gxr2; gsum[3] += gxr3;

            float ig = 1.f / (1.f + expf(-gsum[0]));
            float fg = 1.f / (1.f + expf(-gsum[1]));
            float gg = tanhf(gsum[2]);
            float og = 1.f / (1.f + expf(-gsum[3]));
            float cprev = cs[tid];
            float cnew = fg * cprev + ig * gg;
            float hnew = og * tanhf(cnew);
            cs[tid] = cnew;
            __stcg(&hnxt[(cta * 8 + jl_b) * 32 + b_b], hnew);
            seq[(size_t)t * BH + (size_t)b_b * 1024 + cta * 8 + jl_b] = hnew;
        }

        __threadfence();
        if (t < TT - 1) {
            __syncthreads();
            if (tid == 0) {
                atomicAdd(&g_barcnt, 1u);
                unsigned target = (unsigned)(t + 1) * NCTA;
                volatile unsigned* p = &g_barcnt;
                while (*p < target) { }
            }
            __syncthreads();
        }
    }

    if (tid < 256)
        c_out[(size_t)b_b * 1024 + cta * 8 + jl_b] = cs[tid];
}

// ---------------- helpers ----------------
__global__ void reset_kernel()
{
    int idx = blockIdx.x * blockDim.x + threadIdx.x;
    if (idx == 0) g_barcnt = 0u;
    if (idx < HH * BB) g_hbuf[0][idx] = 0.f;
}

__global__ void finalize(const float* __restrict__ h0seq,
                         const float* __restrict__ out,
                         const float* __restrict__ c0,
                         const float* __restrict__ c1,
                         float* __restrict__ dst)
{
    int idx = blockIdx.x * blockDim.x + threadIdx.x;
    if (idx < BH) {
        dst[idx]          = h0seq[(size_t)(TT - 1) * BH + idx];
        dst[BH + idx]     = out[(size_t)(TT - 1) * BH + idx];
        dst[2 * BH + idx] = c0[idx];
        dst[3 * BH + idx] = c1[idx];
    }
}

// ---------------- launch ----------------
extern "C" void kernel_launch(void* const* d_in, const int* in_sizes, int n_in,
                              void* d_out, int out_size)
{
    const float* x     = (const float*)d_in[0];
    const float* W_ih0 = (const float*)d_in[1];
    const float* W_hh0 = (const float*)d_in[2];
    const float* b_ih0 = (const float*)d_in[3];
    const float* b_hh0 = (const float*)d_in[4];
    const float* W_ih1 = (const float*)d_in[5];
    const float* W_hh1 = (const float*)d_in[6];
    const float* b_ih1 = (const float*)d_in[7];
    const float* b_hh1 = (const float*)d_in[8];
    float* out = (float*)d_out;

    float *gx, *h0seq, *c0, *c1;
    __nv_bfloat16 *ahi, *alo, *whi, *wlo;
    cudaGetSymbolAddress((void**)&gx,    g_gx);
    cudaGetSymbolAddress((void**)&h0seq, g_h0seq);
    cudaGetSymbolAddress((void**)&c0,    g_c0);
    cudaGetSymbolAddress((void**)&c1,    g_c1);
    cudaGetSymbolAddress((void**)&ahi,   g_ahi);
    cudaGetSymbolAddress((void**)&alo,   g_alo);
    cudaGetSymbolAddress((void**)&whi,   g_whi);
    cudaGetSymbolAddress((void**)&wlo,   g_wlo);

    cudaFuncSetAttribute(lstm_layer_persistent,
                         cudaFuncAttributeMaxDynamicSharedMemorySize, SMEM_BYTES);
    cudaFuncSetAttribute(mma_gemm,
                         cudaFuncAttributeMaxDynamicSharedMemorySize, MG_SMEM);

    dim3 tc_grid(G4 / 128, MROWS / 128);   // (32, 128)

    // ---- layer 0 ----
    conv_split<<<MROWS * HH / 256, 256>>>(x, ahi, alo, 1);
    conv_split<<<G4 * HH / 256, 256>>>(W_ih0, whi, wlo, 0);
    mma_gemm<<<tc_grid, 256, MG_SMEM>>>(ahi, alo, whi, wlo, b_ih0, b_hh0, gx);
    reset_kernel<<<128, 256>>>();
    lstm_layer_persistent<<<NCTA, NTHR, SMEM_BYTES>>>(W_hh0, gx, h0seq, c0);

    // ---- layer 1 ----
    conv_split<<<MROWS * HH / 256, 256>>>(h0seq, ahi, alo, 0);
    conv_split<<<G4 * HH / 256, 256>>>(W_ih1, whi, wlo, 0);
    mma_gemm<<<tc_grid, 256, MG_SMEM>>>(ahi, alo, whi, wlo, b_ih1, b_hh1, gx);
    reset_kernel<<<128, 256>>>();
    lstm_layer_persistent<<<NCTA, NTHR, SMEM_BYTES>>>(W_hh1, gx, out, c1);

    // ---- tails ----
    finalize<<<(BH + 255) / 256, 256>>>(h0seq, out, c0, c1, out + (size_t)TT * BH);
}

// round 6
// speedup vs baseline: 1.2844x; 1.0011x over previous
#include <cuda_runtime.h>
#include <cuda_bf16.h>
#include <math.h>
#include <stdint.h>

// Problem constants
#define BB 32
#define TT 512
#define II 1024
#define HH 1024
#define G4 4096
#define MROWS (TT*BB)          // 16384
#define BH (BB*HH)             // 32768
#define NCTA 128
#define NTHR 512

// ---------------- static scratch ----------------
__device__ __align__(128) float g_gx[(size_t)MROWS * G4];       // 256 MB
__device__ __align__(128) float g_h0seq[(size_t)MROWS * HH];    // 64 MB
__device__ __align__(16) __nv_bfloat16 g_ahi[(size_t)MROWS * HH];  // 32 MB
__device__ __align__(16) __nv_bfloat16 g_alo[(size_t)MROWS * HH];  // 32 MB
__device__ __align__(16) __nv_bfloat16 g_whi[(size_t)G4 * HH];     // 8 MB
__device__ __align__(16) __nv_bfloat16 g_wlo[(size_t)G4 * HH];     // 8 MB
__device__ __align__(128) float g_hbuf[2][HH * BB];
__device__ float g_c0[BH];
__device__ float g_c1[BH];
__device__ unsigned int g_barcnt;

// ==================== PTX helpers (plain sm_103-legal only) ====================
__device__ __forceinline__ uint32_t smem_u32(const void* p) {
    uint32_t a;
    asm("{ .reg .u64 t; cvta.to.shared.u64 t, %1; cvt.u32.u64 %0, t; }" : "=r"(a) : "l"(p));
    return a;
}
__device__ __forceinline__ void cp16(uint32_t d, const void* s) {
    asm volatile("cp.async.cg.shared.global [%0], [%1], 16;" :: "r"(d), "l"(s));
}
__device__ __forceinline__ void cp_commit() {
    asm volatile("cp.async.commit_group;" ::: "memory");
}
template <int N>
__device__ __forceinline__ void cp_wait() {
    asm volatile("cp.async.wait_group %0;" :: "n"(N) : "memory");
}
__device__ __forceinline__ void ldsm_x4(uint32_t* r, uint32_t addr) {
    asm volatile("ldmatrix.sync.aligned.m8n8.x4.shared.b16 {%0,%1,%2,%3}, [%4];"
        : "=r"(r[0]), "=r"(r[1]), "=r"(r[2]), "=r"(r[3]) : "r"(addr));
}
__device__ __forceinline__ void ldsm_x2(uint32_t* r, uint32_t addr) {
    asm volatile("ldmatrix.sync.aligned.m8n8.x2.shared.b16 {%0,%1}, [%2];"
        : "=r"(r[0]), "=r"(r[1]) : "r"(addr));
}
__device__ __forceinline__ void mma16816(float* d, const uint32_t* a, const uint32_t* b) {
    asm volatile(
        "mma.sync.aligned.m16n8k16.row.col.f32.bf16.bf16.f32 "
        "{%0,%1,%2,%3}, {%4,%5,%6,%7}, {%8,%9}, {%0,%1,%2,%3};"
        : "+f"(d[0]), "+f"(d[1]), "+f"(d[2]), "+f"(d[3])
        : "r"(a[0]), "r"(a[1]), "r"(a[2]), "r"(a[3]), "r"(b[0]), "r"(b[1]));
}

// ==================== split-bf16 conversion ====================
// gather=1: row m of A maps to x[(m%32)][m/32] (x is [B,T,I]); rows are t*32+b
__global__ __launch_bounds__(256) void conv_split(
    const float* __restrict__ src, __nv_bfloat16* __restrict__ hi,
    __nv_bfloat16* __restrict__ lo, int gather)
{
    size_t idx = (size_t)blockIdx.x * 256 + threadIdx.x;
    size_t soff;
    if (gather) {
        int m = (int)(idx >> 10);
        int k = (int)(idx & 1023);
        soff = (size_t)((m & 31) * 512 + (m >> 5)) * 1024 + k;
    } else {
        soff = idx;
    }
    float v = src[soff];
    __nv_bfloat16 h = __float2bfloat16(v);
    hi[idx] = h;
    lo[idx] = __float2bfloat16(v - __bfloat162float(h));
}

// ==================== HMMA GEMM ====================
// C[16384, 4096] = A[·,1024] @ W[·,1024]^T + b1[n] + b2[n]
// split-bf16: Ahi*Whi + Ahi*Wlo + Alo*Whi, fp32 accumulators.
// BM=128 BN=128 BK=32, 8 warps (2m x 4n), 80B-padded smem rows (conflict-free ldmatrix).
#define ROWB 80
#define TILE_B (128 * ROWB)             // 10240 B per tile
#define STAGE_B (4 * TILE_B)            // 40960 B per stage
#define MG_SMEM (2 * STAGE_B)           // 81920 B

__global__ __launch_bounds__(256) void mma_gemm(
    const __nv_bfloat16* __restrict__ Ahi, const __nv_bfloat16* __restrict__ Alo,
    const __nv_bfloat16* __restrict__ Whi, const __nv_bfloat16* __restrict__ Wlo,
    const float* __restrict__ b1, const float* __restrict__ b2,
    float* __restrict__ C)
{
    extern __shared__ char smraw[];
    const uint32_t sbase = smem_u32(smraw);

    const int tid = threadIdx.x;
    const int wid = tid >> 5;
    const int lid = tid & 31;
    const int wm = wid & 1;              // 2 m-warps (64 rows each)
    const int wn = wid >> 1;             // 4 n-warps (32 cols each)
    const int n0 = blockIdx.x * 128;
    const int m0 = blockIdx.y * 128;

    // per-lane ldmatrix offsets (relative to tile base, bytes)
    uint32_t aoff[4], boff[4];
#pragma unroll
    for (int i = 0; i < 4; i++) {
        int row = wm * 64 + i * 16 + (lid & 15);
        aoff[i] = (uint32_t)(row * ROWB + (lid >> 4) * 16);
    }
#pragma unroll
    for (int j = 0; j < 4; j++) {
        int row = wn * 32 + j * 8 + (lid & 7);
        boff[j] = (uint32_t)(row * ROWB + ((lid >> 3) & 1) * 16);
    }

    float acc[4][4][4];
#pragma unroll
    for (int i = 0; i < 4; i++)
#pragma unroll
        for (int j = 0; j < 4; j++)
#pragma unroll
            for (int q = 0; q < 4; q++) acc[i][j][q] = 0.f;

    // cp.async loader: 2048 x 16B per stage, 8 per thread
    auto issue_stage = [&](int kc, int st) {
        const int k0 = kc * 32;
        const uint32_t sb = sbase + st * STAGE_B;
#pragma unroll
        for (int it = 0; it < 8; it++) {
            int idx = it * 256 + tid;
            int tl = idx >> 9;           // tile 0..3
            int w  = idx & 511;
            int r  = w >> 2;             // row 0..127
            int q  = w & 3;              // 16B chunk within 64B row
            const __nv_bfloat16* src;
            if (tl == 0)      src = Ahi + (size_t)(m0 + r) * 1024 + k0 + q * 8;
            else if (tl == 1) src = Alo + (size_t)(m0 + r) * 1024 + k0 + q * 8;
            else if (tl == 2) src = Whi + (size_t)(n0 + r) * 1024 + k0 + q * 8;
            else              src = Wlo + (size_t)(n0 + r) * 1024 + k0 + q * 8;
            cp16(sb + tl * TILE_B + r * ROWB + q * 16, src);
        }
        cp_commit();
    };

    issue_stage(0, 0);

#pragma unroll 1
    for (int kc = 0; kc < 32; kc++) {
        const int st = kc & 1;
        if (kc + 1 < 32) { issue_stage(kc + 1, st ^ 1); cp_wait<1>(); }
        else             { cp_wait<0>(); }
        __syncthreads();

        const uint32_t sA_hi = sbase + st * STAGE_B;
        const uint32_t sA_lo = sA_hi + TILE_B;
        const uint32_t sW_hi = sA_hi + 2 * TILE_B;
        const uint32_t sW_lo = sA_hi + 3 * TILE_B;

#pragma unroll
        for (int ks = 0; ks < 2; ks++) {
            const uint32_t kb = ks * 32;    // 16 bf16 = 32 bytes
            uint32_t ah[4][4], al[4][4], bh[4][2], bl[4][2];
#pragma unroll
            for (int i = 0; i < 4; i++) ldsm_x4(ah[i], sA_hi + aoff[i] + kb);
#pragma unroll
            for (int i = 0; i < 4; i++) ldsm_x4(al[i], sA_lo + aoff[i] + kb);
#pragma unroll
            for (int j = 0; j < 4; j++) ldsm_x2(bh[j], sW_hi + boff[j] + kb);
#pragma unroll
            for (int j = 0; j < 4; j++) ldsm_x2(bl[j], sW_lo + boff[j] + kb);

#pragma unroll
            for (int i = 0; i < 4; i++)
#pragma unroll
                for (int j = 0; j < 4; j++) {
                    mma16816(acc[i][j], ah[i], bh[j]);
                    mma16816(acc[i][j], ah[i], bl[j]);
                    mma16816(acc[i][j], al[i], bh[j]);
                }
        }
        __syncthreads();
    }

    // epilogue: bias add + direct store
    const int gi = lid >> 2;
    const int ti = lid & 3;
#pragma unroll
    for (int i = 0; i < 4; i++) {
        int mlo = m0 + wm * 64 + i * 16 + gi;
#pragma unroll
        for (int j = 0; j < 4; j++) {
            int n = n0 + wn * 32 + j * 8 + ti * 2;
            float bs0 = __ldg(&b1[n]) + __ldg(&b2[n]);
            float bs1 = __ldg(&b1[n + 1]) + __ldg(&b2[n + 1]);
            float2 v0 = make_float2(acc[i][j][0] + bs0, acc[i][j][1] + bs1);
            float2 v1 = make_float2(acc[i][j][2] + bs0, acc[i][j][3] + bs1);
            *(float2*)&C[(size_t)mlo * G4 + n] = v0;
            *(float2*)&C[(size_t)(mlo + 8) * G4 + n] = v1;
        }
    }
}

// ==================== persistent LSTM layer (validated in R2) ====================
#define WS_OFF   0
#define HS_OFF   (WS_OFF + 1024*32)
#define PART_OFF (HS_OFF + 128*32)
#define CS_OFF   (PART_OFF + 8*32*33)
#define SMEM_FLOATS (CS_OFF + 256)
#define SMEM_BYTES (SMEM_FLOATS * 4)

__global__ void __launch_bounds__(NTHR, 1) lstm_layer_persistent(
    const float* __restrict__ Whh,
    const float* __restrict__ gx,
    float* __restrict__ seq,
    float* __restrict__ c_out)
{
    extern __shared__ float sm[];
    float* Ws   = sm + WS_OFF;
    float* hs   = sm + HS_OFF;
    float* part = sm + PART_OFF;
    float* cs   = sm + CS_OFF;

    const int tid = threadIdx.x;
    const int cta = blockIdx.x;
    const int s  = tid >> 6;
    const int u  = tid & 63;
    const int ty = u >> 3;
    const int tx = u & 7;

    for (int idx = tid; idx < 32 * 1024; idx += NTHR) {
        int r = idx >> 10;
        int k = idx & 1023;
        int g = r >> 3, jl = r & 7;
        Ws[k * 32 + r] = Whh[(size_t)(g * 1024 + cta * 8 + jl) * HH + k];
    }
    if (tid < 256) cs[tid] = 0.f;
    __syncthreads();

    const int jl_b = tid & 7;
    const int b_b  = tid >> 3;

    float acc[4][4];

    for (int t = 0; t < TT; t++) {
        const float* hcur = g_hbuf[t & 1];
        float*       hnxt = g_hbuf[(t + 1) & 1];

        float gxr0 = 0.f, gxr1 = 0.f, gxr2 = 0.f, gxr3 = 0.f;
        if (tid < 256) {
            const float* gp = gx + (size_t)(t * 32 + b_b) * G4 + cta * 8 + jl_b;
            gxr0 = __ldg(gp);
            gxr1 = __ldg(gp + 1024);
            gxr2 = __ldg(gp + 2048);
            gxr3 = __ldg(gp + 3072);
        }

#pragma unroll
        for (int i = 0; i < 4; i++)
#pragma unroll
            for (int j = 0; j < 4; j++) acc[i][j] = 0.f;

        float4 pre0 = __ldcg((const float4*)hcur + tid * 2);
        float4 pre1 = __ldcg((const float4*)hcur + tid * 2 + 1);

        for (int cn = 0; cn < 8; cn++) {
            __syncthreads();
            ((float4*)hs)[tid * 2]     = pre0;
            ((float4*)hs)[tid * 2 + 1] = pre1;
            __syncthreads();
            if (cn < 7) {
                const float4* src = (const float4*)(hcur + (cn + 1) * 4096);
                pre0 = __ldcg(src + tid * 2);
                pre1 = __ldcg(src + tid * 2 + 1);
            }
            const float* WsK = Ws + (cn * 128 + s * 16) * 32;
            const float* hsK = hs + (s * 16) * 32;
#pragma unroll
            for (int kl = 0; kl < 16; kl++) {
                float4 wv = *(const float4*)(WsK + kl * 32 + ty * 4);
                float4 hv = *(const float4*)(hsK + kl * 32 + tx * 4);
                acc[0][0] = fmaf(wv.x, hv.x, acc[0][0]);
                acc[0][1] = fmaf(wv.x, hv.y, acc[0][1]);
                acc[0][2] = fmaf(wv.x, hv.z, acc[0][2]);
                acc[0][3] = fmaf(wv.x, hv.w, acc[0][3]);
                acc[1][0] = fmaf(wv.y, hv.x, acc[1][0]);
                acc[1][1] = fmaf(wv.y, hv.y, acc[1][1]);
                acc[1][2] = fmaf(wv.y, hv.z, acc[1][2]);
                acc[1][3] = fmaf(wv.y, hv.w, acc[1][3]);
                acc[2][0] = fmaf(wv.z, hv.x, acc[2][0]);
                acc[2][1] = fmaf(wv.z, hv.y, acc[2][1]);
                acc[2][2] = fmaf(wv.z, hv.z, acc[2][2]);
                acc[2][3] = fmaf(wv.z, hv.w, acc[2][3]);
                acc[3][0] = fmaf(wv.w, hv.x, acc[3][0]);
                acc[3][1] = fmaf(wv.w, hv.y, acc[3][1]);
                acc[3][2] = fmaf(wv.w, hv.z, acc[3][2]);
                acc[3][3] = fmaf(wv.w, hv.w, acc[3][3]);
            }
        }

#pragma unroll
        for (int i = 0; i < 4; i++)
#pragma unroll
            for (int j = 0; j < 4; j++)
                part[(s * 32 + ty * 4 + i) * 33 + tx * 4 + j] = acc[i][j];
        __syncthreads();

        if (tid < 256) {
            float gsum[4];
#pragma unroll
            for (int g = 0; g < 4; g++) {
                float v = 0.f;
#pragma unroll
                for (int ss = 0; ss < 8; ss++)
                    v += part[(ss * 32 + g * 8 + jl_b) * 33 + b_b];
                gsum[g] = v;
            }
            gsum[0] += gxr0; gsum[1] += gxr1; gsum[2] += gxr2; gsum[3] += gxr3;

            float ig = 1.f / (1.f + expf(-gsum[0]));
            float fg = 1.f / (1.f + expf(-gsum[1]));
            float gg = tanhf(gsum[2]);
            float og = 1.f / (1.f + expf(-gsum[3]));
            float cprev = cs[tid];
            float cnew = fg * cprev + ig * gg;
            float hnew = og * tanhf(cnew);
            cs[tid] = cnew;
            __stcg(&hnxt[(cta * 8 + jl_b) * 32 + b_b], hnew);
            seq[(size_t)t * BH + (size_t)b_b * 1024 + cta * 8 + jl_b] = hnew;
        }

        __threadfence();
        if (t < TT - 1) {
            __syncthreads();
            if (tid == 0) {
                atomicAdd(&g_barcnt, 1u);
                unsigned target = (unsigned)(t + 1) * NCTA;
                volatile unsigned* p = &g_barcnt;
                while (*p < target) { }
            }
            __syncthreads();
        }
    }

    if (tid < 256)
        c_out[(size_t)b_b * 1024 + cta * 8 + jl_b] = cs[tid];
}

// ---------------- helpers ----------------
__global__ void reset_kernel()
{
    int idx = blockIdx.x * blockDim.x + threadIdx.x;
    if (idx == 0) g_barcnt = 0u;
    if (idx < HH * BB) g_hbuf[0][idx] = 0.f;
}

__global__ void finalize(const float* __restrict__ h0seq,
                         const float* __restrict__ out,
                         const float* __restrict__ c0,
                         const float* __restrict__ c1,
                         float* __restrict__ dst)
{
    int idx = blockIdx.x * blockDim.x + threadIdx.x;
    if (idx < BH) {
        dst[idx]          = h0seq[(size_t)(TT - 1) * BH + idx];
        dst[BH + idx]     = out[(size_t)(TT - 1) * BH + idx];
        dst[2 * BH + idx] = c0[idx];
        dst[3 * BH + idx] = c1[idx];
    }
}

// ---------------- launch ----------------
extern "C" void kernel_launch(void* const* d_in, const int* in_sizes, int n_in,
                              void* d_out, int out_size)
{
    const float* x     = (const float*)d_in[0];
    const float* W_ih0 = (const float*)d_in[1];
    const float* W_hh0 = (const float*)d_in[2];
    const float* b_ih0 = (const float*)d_in[3];
    const float* b_hh0 = (const float*)d_in[4];
    const float* W_ih1 = (const float*)d_in[5];
    const float* W_hh1 = (const float*)d_in[6];
    const float* b_ih1 = (const float*)d_in[7];
    const float* b_hh1 = (const float*)d_in[8];
    float* out = (float*)d_out;

    float *gx, *h0seq, *c0, *c1;
    __nv_bfloat16 *ahi, *alo, *whi, *wlo;
    cudaGetSymbolAddress((void**)&gx,    g_gx);
    cudaGetSymbolAddress((void**)&h0seq, g_h0seq);
    cudaGetSymbolAddress((void**)&c0,    g_c0);
    cudaGetSymbolAddress((void**)&c1,    g_c1);
    cudaGetSymbolAddress((void**)&ahi,   g_ahi);
    cudaGetSymbolAddress((void**)&alo,   g_alo);
    cudaGetSymbolAddress((void**)&whi,   g_whi);
    cudaGetSymbolAddress((void**)&wlo,   g_wlo);

    cudaFuncSetAttribute(lstm_layer_persistent,
                         cudaFuncAttributeMaxDynamicSharedMemorySize, SMEM_BYTES);
    cudaFuncSetAttribute(mma_gemm,
                         cudaFuncAttributeMaxDynamicSharedMemorySize, MG_SMEM);

    dim3 tc_grid(G4 / 128, MROWS / 128);   // (32, 128)

    // ---- layer 0 ----
    conv_split<<<MROWS * HH / 256, 256>>>(x, ahi, alo, 1);
    conv_split<<<G4 * HH / 256, 256>>>(W_ih0, whi, wlo, 0);
    mma_gemm<<<tc_grid, 256, MG_SMEM>>>(ahi, alo, whi, wlo, b_ih0, b_hh0, gx);
    reset_kernel<<<128, 256>>>();
    lstm_layer_persistent<<<NCTA, NTHR, SMEM_BYTES>>>(W_hh0, gx, h0seq, c0);

    // ---- layer 1 ----
    conv_split<<<MROWS * HH / 256, 256>>>(h0seq, ahi, alo, 0);
    conv_split<<<G4 * HH / 256, 256>>>(W_ih1, whi, wlo, 0);
    mma_gemm<<<tc_grid, 256, MG_SMEM>>>(ahi, alo, whi, wlo, b_ih1, b_hh1, gx);
    reset_kernel<<<128, 256>>>();
    lstm_layer_persistent<<<NCTA, NTHR, SMEM_BYTES>>>(W_hh1, gx, out, c1);

    // ---- tails ----
    finalize<<<(BH + 255) / 256, 256>>>(h0seq, out, c0, c1, out + (size_t)TT * BH);
}

// round 7
// speedup vs baseline: 1.8576x; 1.4463x over previous
#include <cuda_runtime.h>
#include <cuda_bf16.h>
#include <math.h>
#include <stdint.h>

// Problem constants
#define BB 32
#define TT 512
#define II 1024
#define HH 1024
#define G4 4096
#define MROWS (TT*BB)          // 16384
#define BH (BB*HH)             // 32768
#define NCTA 128
#define NTHR 256

// ---------------- static scratch ----------------
__device__ __align__(128) float g_gx[(size_t)MROWS * G4];       // 256 MB
__device__ __align__(128) float g_h0seq[(size_t)MROWS * HH];    // 64 MB
__device__ __align__(16) __nv_bfloat16 g_ahi[(size_t)MROWS * HH];
__device__ __align__(16) __nv_bfloat16 g_alo[(size_t)MROWS * HH];
__device__ __align__(16) __nv_bfloat16 g_whi[(size_t)G4 * HH];
__device__ __align__(16) __nv_bfloat16 g_wlo[(size_t)G4 * HH];
__device__ __align__(128) __nv_bfloat16 g_hb16[2][2][BH];       // [buf][hi/lo][b][k]
__device__ float g_c0[BH];
__device__ float g_c1[BH];
__device__ unsigned int g_barcnt;

// ==================== PTX helpers (plain sm_103-legal only) ====================
__device__ __forceinline__ uint32_t smem_u32(const void* p) {
    uint32_t a;
    asm("{ .reg .u64 t; cvta.to.shared.u64 t, %1; cvt.u32.u64 %0, t; }" : "=r"(a) : "l"(p));
    return a;
}
__device__ __forceinline__ void cp16(uint32_t d, const void* s) {
    asm volatile("cp.async.cg.shared.global [%0], [%1], 16;" :: "r"(d), "l"(s));
}
__device__ __forceinline__ void cp_commit() {
    asm volatile("cp.async.commit_group;" ::: "memory");
}
template <int N>
__device__ __forceinline__ void cp_wait() {
    asm volatile("cp.async.wait_group %0;" :: "n"(N) : "memory");
}
__device__ __forceinline__ void ldsm_x4(uint32_t* r, uint32_t addr) {
    asm volatile("ldmatrix.sync.aligned.m8n8.x4.shared.b16 {%0,%1,%2,%3}, [%4];"
        : "=r"(r[0]), "=r"(r[1]), "=r"(r[2]), "=r"(r[3]) : "r"(addr));
}
__device__ __forceinline__ void ldsm_x2(uint32_t* r, uint32_t addr) {
    asm volatile("ldmatrix.sync.aligned.m8n8.x2.shared.b16 {%0,%1}, [%2];"
        : "=r"(r[0]), "=r"(r[1]) : "r"(addr));
}
__device__ __forceinline__ void mma16816(float* d, const uint32_t* a, const uint32_t* b) {
    asm volatile(
        "mma.sync.aligned.m16n8k16.row.col.f32.bf16.bf16.f32 "
        "{%0,%1,%2,%3}, {%4,%5,%6,%7}, {%8,%9}, {%0,%1,%2,%3};"
        : "+f"(d[0]), "+f"(d[1]), "+f"(d[2]), "+f"(d[3])
        : "r"(a[0]), "r"(a[1]), "r"(a[2]), "r"(a[3]), "r"(b[0]), "r"(b[1]));
}

// ==================== split-bf16 conversion ====================
__global__ __launch_bounds__(256) void conv_split(
    const float* __restrict__ src, __nv_bfloat16* __restrict__ hi,
    __nv_bfloat16* __restrict__ lo, int gather)
{
    size_t idx = (size_t)blockIdx.x * 256 + threadIdx.x;
    size_t soff;
    if (gather) {
        int m = (int)(idx >> 10);
        int k = (int)(idx & 1023);
        soff = (size_t)((m & 31) * 512 + (m >> 5)) * 1024 + k;
    } else {
        soff = idx;
    }
    float v = src[soff];
    __nv_bfloat16 h = __float2bfloat16(v);
    hi[idx] = h;
    lo[idx] = __float2bfloat16(v - __bfloat162float(h));
}

// ==================== HMMA big GEMM (validated in R6) ====================
#define ROWB 80
#define TILE_B (128 * ROWB)
#define STAGE_B (4 * TILE_B)
#define MG_SMEM (2 * STAGE_B)

__global__ __launch_bounds__(256) void mma_gemm(
    const __nv_bfloat16* __restrict__ Ahi, const __nv_bfloat16* __restrict__ Alo,
    const __nv_bfloat16* __restrict__ Whi, const __nv_bfloat16* __restrict__ Wlo,
    const float* __restrict__ b1, const float* __restrict__ b2,
    float* __restrict__ C)
{
    extern __shared__ char smraw[];
    const uint32_t sbase = smem_u32(smraw);

    const int tid = threadIdx.x;
    const int wid = tid >> 5;
    const int lid = tid & 31;
    const int wm = wid & 1;
    const int wn = wid >> 1;
    const int n0 = blockIdx.x * 128;
    const int m0 = blockIdx.y * 128;

    uint32_t aoff[4], boff[4];
#pragma unroll
    for (int i = 0; i < 4; i++) {
        int row = wm * 64 + i * 16 + (lid & 15);
        aoff[i] = (uint32_t)(row * ROWB + (lid >> 4) * 16);
    }
#pragma unroll
    for (int j = 0; j < 4; j++) {
        int row = wn * 32 + j * 8 + (lid & 7);
        boff[j] = (uint32_t)(row * ROWB + ((lid >> 3) & 1) * 16);
    }

    float acc[4][4][4];
#pragma unroll
    for (int i = 0; i < 4; i++)
#pragma unroll
        for (int j = 0; j < 4; j++)
#pragma unroll
            for (int q = 0; q < 4; q++) acc[i][j][q] = 0.f;

    auto issue_stage = [&](int kc, int st) {
        const int k0 = kc * 32;
        const uint32_t sb = sbase + st * STAGE_B;
#pragma unroll
        for (int it = 0; it < 8; it++) {
            int idx = it * 256 + tid;
            int tl = idx >> 9;
            int w  = idx & 511;
            int r  = w >> 2;
            int q  = w & 3;
            const __nv_bfloat16* src;
            if (tl == 0)      src = Ahi + (size_t)(m0 + r) * 1024 + k0 + q * 8;
            else if (tl == 1) src = Alo + (size_t)(m0 + r) * 1024 + k0 + q * 8;
            else if (tl == 2) src = Whi + (size_t)(n0 + r) * 1024 + k0 + q * 8;
            else              src = Wlo + (size_t)(n0 + r) * 1024 + k0 + q * 8;
            cp16(sb + tl * TILE_B + r * ROWB + q * 16, src);
        }
        cp_commit();
    };

    issue_stage(0, 0);

#pragma unroll 1
    for (int kc = 0; kc < 32; kc++) {
        const int st = kc & 1;
        if (kc + 1 < 32) { issue_stage(kc + 1, st ^ 1); cp_wait<1>(); }
        else             { cp_wait<0>(); }
        __syncthreads();

        const uint32_t sA_hi = sbase + st * STAGE_B;
        const uint32_t sA_lo = sA_hi + TILE_B;
        const uint32_t sW_hi = sA_hi + 2 * TILE_B;
        const uint32_t sW_lo = sA_hi + 3 * TILE_B;

#pragma unroll
        for (int ks = 0; ks < 2; ks++) {
            const uint32_t kb = ks * 32;
            uint32_t ah[4][4], al[4][4], bh[4][2], bl[4][2];
#pragma unroll
            for (int i = 0; i < 4; i++) ldsm_x4(ah[i], sA_hi + aoff[i] + kb);
#pragma unroll
            for (int i = 0; i < 4; i++) ldsm_x4(al[i], sA_lo + aoff[i] + kb);
#pragma unroll
            for (int j = 0; j < 4; j++) ldsm_x2(bh[j], sW_hi + boff[j] + kb);
#pragma unroll
            for (int j = 0; j < 4; j++) ldsm_x2(bl[j], sW_lo + boff[j] + kb);

#pragma unroll
            for (int i = 0; i < 4; i++)
#pragma unroll
                for (int j = 0; j < 4; j++) {
                    mma16816(acc[i][j], ah[i], bh[j]);
                    mma16816(acc[i][j], ah[i], bl[j]);
                    mma16816(acc[i][j], al[i], bh[j]);
                }
        }
        __syncthreads();
    }

    const int gi = lid >> 2;
    const int ti = lid & 3;
#pragma unroll
    for (int i = 0; i < 4; i++) {
        int mlo = m0 + wm * 64 + i * 16 + gi;
#pragma unroll
        for (int j = 0; j < 4; j++) {
            int n = n0 + wn * 32 + j * 8 + ti * 2;
            float bs0 = __ldg(&b1[n]) + __ldg(&b2[n]);
            float bs1 = __ldg(&b1[n + 1]) + __ldg(&b2[n + 1]);
            float2 v0 = make_float2(acc[i][j][0] + bs0, acc[i][j][1] + bs1);
            float2 v1 = make_float2(acc[i][j][2] + bs0, acc[i][j][3] + bs1);
            *(float2*)&C[(size_t)mlo * G4 + n] = v0;
            *(float2*)&C[(size_t)(mlo + 8) * G4 + n] = v1;
        }
    }
}

// ==================== persistent LSTM layer — HMMA recurrence ====================
// Per CTA: gates[32 rows x 32 batch] = Whh_slice[32,1024] (smem bf16 hi/lo)
//          @ h[1024,32] (global bf16 hi/lo, cp.async in 128-k chunks).
// smem byte layout:
#define WROWB 2064                       // 1024 bf16 + 16B pad (conflict-free ldmatrix)
#define LW_HI 0                          // 32 * 2064 = 66048
#define LW_LO 66048
#define HROWB 272                        // 128 bf16 + 16B pad
#define HTILE (32 * HROWB)               // 8704
#define LH_BASE 132096                   // 2 stages x (hi+lo) = 2 x 17408
#define H_STAGE (2 * HTILE)              // 17408
#define LGATES (LH_BASE + 2 * H_STAGE)   // 166912 : gates[32][33] f32 = 4224
#define LCS (LGATES + 4224)              // 171136 : cs[256] f32
#define LSTM_SMEM (LCS + 1024)           // 172160 B

__global__ void __launch_bounds__(NTHR, 1) lstm_layer_persistent(
    const float* __restrict__ Whh,
    const float* __restrict__ gx,
    float* __restrict__ seq,
    float* __restrict__ c_out)
{
    extern __shared__ char smc[];
    const uint32_t sbase = smem_u32(smc);
    float* gates = (float*)(smc + LGATES);
    float* cs    = (float*)(smc + LCS);

    const int tid = threadIdx.x;
    const int wid = tid >> 5;
    const int lid = tid & 31;
    const int cta = blockIdx.x;           // owns hidden cols j = cta*8 .. cta*8+7
    const int wm  = wid & 1;              // m-tile (16 gate-rows)
    const int wn  = wid >> 1;             // n-tile (8 batches)

    // ---- one-time: W slice -> smem, split bf16 hi/lo. rows r = g*8+jl ----
    for (int idx = tid; idx < 32 * 1024; idx += NTHR) {
        int r = idx >> 10;
        int k = idx & 1023;
        int g = r >> 3, jl = r & 7;
        float v = Whh[(size_t)(g * 1024 + cta * 8 + jl) * HH + k];
        __nv_bfloat16 hi = __float2bfloat16(v);
        __nv_bfloat16 lo = __float2bfloat16(v - __bfloat162float(hi));
        *(__nv_bfloat16*)(smc + LW_HI + r * WROWB + k * 2) = hi;
        *(__nv_bfloat16*)(smc + LW_LO + r * WROWB + k * 2) = lo;
    }
    cs[tid] = 0.f;
    __syncthreads();

    // per-lane ldmatrix offsets
    const uint32_t a_off = (uint32_t)((wm * 16 + (lid & 15)) * WROWB + (lid >> 4) * 16);
    const uint32_t b_off = (uint32_t)((wn * 8 + (lid & 7)) * HROWB + ((lid >> 3) & 1) * 16);

    const int jl_b = tid & 7;
    const int b_b  = tid >> 3;

    for (int t = 0; t < TT; t++) {
        const __nv_bfloat16* hb_cur = &g_hb16[t & 1][0][0];        // [hi/lo][b][k]
        __nv_bfloat16*       hb_nxt = &g_hb16[(t + 1) & 1][0][0];

        // h chunk loader: chunk c covers k = c*128 .. +127 (hi then lo)
        auto issue_h = [&](int c, int st) {
            const uint32_t sb = sbase + LH_BASE + st * H_STAGE;
#pragma unroll
            for (int it = 0; it < 4; it++) {
                int idx = it * 256 + tid;
                int part = idx >> 9;       // 0 = hi, 1 = lo
                int w = idx & 511;
                int b = w >> 4;
                int q = w & 15;
                cp16(sb + part * HTILE + b * HROWB + q * 16,
                     hb_cur + (size_t)part * BH + b * 1024 + c * 128 + q * 8);
            }
            cp_commit();
        };

        // prefetch gx (+biases already folded in)
        const float* gp = gx + (size_t)(t * 32 + b_b) * G4 + cta * 8 + jl_b;
        float gxr0 = __ldg(gp);
        float gxr1 = __ldg(gp + 1024);
        float gxr2 = __ldg(gp + 2048);
        float gxr3 = __ldg(gp + 3072);

        float acc[4] = {0.f, 0.f, 0.f, 0.f};

        issue_h(0, 0);
#pragma unroll 1
        for (int c = 0; c < 8; c++) {
            const int st = c & 1;
            if (c + 1 < 8) { issue_h(c + 1, st ^ 1); cp_wait<1>(); }
            else           { cp_wait<0>(); }
            __syncthreads();

            const uint32_t hst = sbase + LH_BASE + st * H_STAGE;
#pragma unroll
            for (int ks = 0; ks < 8; ks++) {
                uint32_t ah[4], al[4], bh[2], bl[2];
                const uint32_t ka = (uint32_t)((c * 128 + ks * 16) * 2);
                ldsm_x4(ah, sbase + LW_HI + a_off + ka);
                ldsm_x4(al, sbase + LW_LO + a_off + ka);
                ldsm_x2(bh, hst + b_off + ks * 32);
                ldsm_x2(bl, hst + HTILE + b_off + ks * 32);
                mma16816(acc, ah, bh);
                mma16816(acc, ah, bl);
                mma16816(acc, al, bh);
            }
            __syncthreads();
        }

        // exchange gates through smem
        {
            int r0 = wm * 16 + (lid >> 2);
            int c0 = wn * 8 + (lid & 3) * 2;
            gates[r0 * 33 + c0]           = acc[0];
            gates[r0 * 33 + c0 + 1]       = acc[1];
            gates[(r0 + 8) * 33 + c0]     = acc[2];
            gates[(r0 + 8) * 33 + c0 + 1] = acc[3];
        }
        __syncthreads();

        // pointwise: gate order i,f,g,o at rows g*8+jl
        {
            float g0 = gates[jl_b * 33 + b_b]        + gxr0;
            float g1 = gates[(8 + jl_b) * 33 + b_b]  + gxr1;
            float g2 = gates[(16 + jl_b) * 33 + b_b] + gxr2;
            float g3 = gates[(24 + jl_b) * 33 + b_b] + gxr3;

            float ig = 1.f / (1.f + expf(-g0));
            float fg = 1.f / (1.f + expf(-g1));
            float gg = tanhf(g2);
            float og = 1.f / (1.f + expf(-g3));
            float cnew = fg * cs[tid] + ig * gg;
            float hnew = og * tanhf(cnew);
            cs[tid] = cnew;

            __nv_bfloat16 hh = __float2bfloat16(hnew);
            __nv_bfloat16 hl = __float2bfloat16(hnew - __bfloat162float(hh));
            int j = cta * 8 + jl_b;
            hb_nxt[b_b * 1024 + j]      = hh;
            hb_nxt[BH + b_b * 1024 + j] = hl;
            seq[(size_t)t * BH + (size_t)b_b * 1024 + j] = hnew;
        }

        __threadfence();
        if (t < TT - 1) {
            __syncthreads();
            if (tid == 0) {
                atomicAdd(&g_barcnt, 1u);
                unsigned target = (unsigned)(t + 1) * NCTA;
                volatile unsigned* p = &g_barcnt;
                while (*p < target) { }
            }
            __syncthreads();
        }
    }

    c_out[(size_t)b_b * 1024 + cta * 8 + jl_b] = cs[tid];
}

// ---------------- helpers ----------------
__global__ void reset_kernel()
{
    int idx = blockIdx.x * blockDim.x + threadIdx.x;   // 32768 threads
    if (idx == 0) g_barcnt = 0u;
    if (idx < 32768) ((uint32_t*)g_hb16)[idx] = 0u;    // zeros buf 0 (hi+lo)
}

__global__ void finalize(const float* __restrict__ h0seq,
                         const float* __restrict__ out,
                         const float* __restrict__ c0,
                         const float* __restrict__ c1,
                         float* __restrict__ dst)
{
    int idx = blockIdx.x * blockDim.x + threadIdx.x;
    if (idx < BH) {
        dst[idx]          = h0seq[(size_t)(TT - 1) * BH + idx];
        dst[BH + idx]     = out[(size_t)(TT - 1) * BH + idx];
        dst[2 * BH + idx] = c0[idx];
        dst[3 * BH + idx] = c1[idx];
    }
}

// ---------------- launch ----------------
extern "C" void kernel_launch(void* const* d_in, const int* in_sizes, int n_in,
                              void* d_out, int out_size)
{
    const float* x     = (const float*)d_in[0];
    const float* W_ih0 = (const float*)d_in[1];
    const float* W_hh0 = (const float*)d_in[2];
    const float* b_ih0 = (const float*)d_in[3];
    const float* b_hh0 = (const float*)d_in[4];
    const float* W_ih1 = (const float*)d_in[5];
    const float* W_hh1 = (const float*)d_in[6];
    const float* b_ih1 = (const float*)d_in[7];
    const float* b_hh1 = (const float*)d_in[8];
    float* out = (float*)d_out;

    float *gx, *h0seq, *c0, *c1;
    __nv_bfloat16 *ahi, *alo, *whi, *wlo;
    cudaGetSymbolAddress((void**)&gx,    g_gx);
    cudaGetSymbolAddress((void**)&h0seq, g_h0seq);
    cudaGetSymbolAddress((void**)&c0,    g_c0);
    cudaGetSymbolAddress((void**)&c1,    g_c1);
    cudaGetSymbolAddress((void**)&ahi,   g_ahi);
    cudaGetSymbolAddress((void**)&alo,   g_alo);
    cudaGetSymbolAddress((void**)&whi,   g_whi);
    cudaGetSymbolAddress((void**)&wlo,   g_wlo);

    cudaFuncSetAttribute(lstm_layer_persistent,
                         cudaFuncAttributeMaxDynamicSharedMemorySize, LSTM_SMEM);
    cudaFuncSetAttribute(mma_gemm,
                         cudaFuncAttributeMaxDynamicSharedMemorySize, MG_SMEM);

    dim3 tc_grid(G4 / 128, MROWS / 128);   // (32, 128)

    // ---- layer 0 ----
    conv_split<<<MROWS * HH / 256, 256>>>(x, ahi, alo, 1);
    conv_split<<<G4 * HH / 256, 256>>>(W_ih0, whi, wlo, 0);
    mma_gemm<<<tc_grid, 256, MG_SMEM>>>(ahi, alo, whi, wlo, b_ih0, b_hh0, gx);
    reset_kernel<<<128, 256>>>();
    lstm_layer_persistent<<<NCTA, NTHR, LSTM_SMEM>>>(W_hh0, gx, h0seq, c0);

    // ---- layer 1 ----
    conv_split<<<MROWS * HH / 256, 256>>>(h0seq, ahi, alo, 0);
    conv_split<<<G4 * HH / 256, 256>>>(W_ih1, whi, wlo, 0);
    mma_gemm<<<tc_grid, 256, MG_SMEM>>>(ahi, alo, whi, wlo, b_ih1, b_hh1, gx);
    reset_kernel<<<128, 256>>>();
    lstm_layer_persistent<<<NCTA, NTHR, LSTM_SMEM>>>(W_hh1, gx, out, c1);

    // ---- tails ----
    finalize<<<(BH + 255) / 256, 256>>>(h0seq, out, c0, c1, out + (size_t)TT * BH);
}